// round 5
// baseline (speedup 1.0000x reference)
#include <cuda_runtime.h>
#include <cuda_bf16.h>

#define BQ 1024

// ---------- packed fp32x2 FMA (Blackwell FFMA2) ----------
union F2U { float2 f; unsigned long long u; };
__device__ __forceinline__ float2 ffma2(float2 a, float2 b, float2 c) {
    F2U A, B, C, D;
    A.f = a; B.f = b; C.f = c;
    asm("fma.rn.f32x2 %0, %1, %2, %3;" : "=l"(D.u) : "l"(A.u), "l"(B.u), "l"(C.u));
    return D.f;
}
__device__ __forceinline__ float2 mf2(float x, float y) { float2 r; r.x = x; r.y = y; return r; }

// ---------- cp.async helpers ----------
__device__ __forceinline__ unsigned su32(const void* p) {
    return (unsigned)__cvta_generic_to_shared(p);
}
#define CP16(dst_u32, src_ptr) \
    asm volatile("cp.async.cg.shared.global [%0], [%1], 16;\n" :: "r"(dst_u32), "l"(src_ptr))
#define CPCOMMIT() asm volatile("cp.async.commit_group;\n" ::: "memory")
#define CPWAIT0()  asm volatile("cp.async.wait_group 0;\n" ::: "memory")
#define PAIRBAR(id) asm volatile("bar.sync %0, 64;" :: "r"(id) : "memory")

// Folded-weight device globals
__device__ float g_s[64];      // strength @ str_w + str_b
__device__ float g_AkT[512];   // [j][c] = sum_d Wk[d][c] * attn_w1[d][j]
__device__ float g_AqT[512];   // [j][c]
__device__ float g_ApT[64];    // [j][i] = sum_d pos_w2[i][d] * attn_w1[d][j]
__device__ float g_cb[8];      // [j]

__global__ void precompute_kernel(
    const float* __restrict__ strength, const float* __restrict__ str_w,
    const float* __restrict__ str_b,
    const float* __restrict__ q_tbl, const float* __restrict__ k_tbl,
    const float* __restrict__ attn_w1, const float* __restrict__ attn_b1,
    const float* __restrict__ pos_w2, const float* __restrict__ pos_b2,
    const int* __restrict__ embed_id)
{
    const int t = threadIdx.x;
    const int e = embed_id[0];

    if (t < 64) {
        float acc = str_b[t];
        for (int i = 0; i < 512; ++i) acc += strength[i] * str_w[i * 64 + t];
        g_s[t] = acc;
    }
    for (int idx = t; idx < 512; idx += 256) {
        const int j = idx >> 6, c = idx & 63;
        float ak = 0.f, aq = 0.f;
        for (int dd = 0; dd < 64; ++dd) {
            const float w1 = attn_w1[dd * 8 + j];
            ak += k_tbl[e * 4096 + dd * 64 + c] * w1;
            aq += q_tbl[e * 4096 + dd * 64 + c] * w1;
        }
        g_AkT[idx] = ak;
        g_AqT[idx] = aq;
    }
    if (t < 64) {
        const int j = t >> 3, i = t & 7;
        float ap = 0.f;
        for (int dd = 0; dd < 64; ++dd) ap += pos_w2[i * 64 + dd] * attn_w1[dd * 8 + j];
        g_ApT[j * 8 + i] = ap;
    }
    if (t < 8) {
        float cb = attn_b1[t];
        for (int dd = 0; dd < 64; ++dd) cb += pos_b2[dd] * attn_w1[dd * 8 + t];
        g_cb[t] = cb;
    }
}

// 128 threads per CTA; each CTA handles 16 n-rows (4 chunks of 4 rows).
// Pair p = tid>>6 (64 threads) owns rows {p, p+2} of each chunk; all
// inter-phase dependencies stay inside a pair -> named 64-thread barriers.
__global__ __launch_bounds__(128, 4)
void attn_main(
    const float* __restrict__ q, const float* __restrict__ k,
    const float* __restrict__ pos,
    const float* __restrict__ v_tbl,
    const float* __restrict__ pos_w1, const float* __restrict__ pos_b1,
    const float* __restrict__ pos_w2, const float* __restrict__ pos_b2,
    const float* __restrict__ attn_w2, const float* __restrict__ attn_b2,
    const float* __restrict__ out_w, const float* __restrict__ out_b,
    const int* __restrict__ mask, const int* __restrict__ embed_id,
    float* __restrict__ out)
{
    __shared__ float s_ow[4096];                         // out_w [c][d]
    __shared__ __align__(16) float s_k[2][32 * 68];      // k rows (stride 68), dbl-buffered
    __shared__ __align__(16) float s_akT[8 * 68];        // [j][c]
    __shared__ __align__(16) float s_aqT[8 * 68];        // [j][c]
    __shared__ __align__(16) float s_q[2][256];
    __shared__ __align__(16) float s_pos[2][128];        // [rv][4]
    __shared__ __align__(16) int   s_mask[2][32];
    __shared__ __align__(16) float s_ph[256];            // [rv][8]
    __shared__ __align__(16) float s_hh[256];            // [rv][8]
    __shared__ __align__(16) float s_apT[64];            // [j][i]
    __shared__ float s_x[256];                           // [row][d]
    __shared__ float s_h1q[32];                          // [row][j]
    __shared__ float s_pw1[32];

    const int tid = threadIdx.x;
    const int b = blockIdx.x;
    const int nbase = blockIdx.y * 16;
    const int e = embed_id[0];

    // ---- prefetch chunk 0 (4 rows) ----
    {
        const long base_n = (long)b * 64 + nbase;
        const float4* kg = (const float4*)(k + base_n * 512);
        #pragma unroll
        for (int r = 0; r < 4; ++r) {
            const int i = tid + 128 * r;                 // 0..511 float4s
            CP16(su32(&s_k[0][(i >> 4) * 68 + (i & 15) * 4]), kg + i);
        }
        if (tid < 64) CP16(su32(&s_q[0][tid * 4]),   (const float4*)(q + base_n * 64) + tid);
        if (tid < 32) CP16(su32(&s_pos[0][tid * 4]), (const float4*)(pos + base_n * 32) + tid);
        if (tid < 8)  CP16(su32(&s_mask[0][tid * 4]), (const int4*)(mask + base_n * 8) + tid);
        CPCOMMIT();
    }

    // ---- one-time staging ----
    for (int i = tid; i < 4096; i += 128) s_ow[i] = out_w[i];
    for (int i = tid; i < 512; i += 128) {
        const int jj = i >> 6, c = i & 63;
        s_akT[jj * 68 + c] = g_AkT[i];
        s_aqT[jj * 68 + c] = g_AqT[i];
    }
    if (tid < 64) s_apT[tid] = g_ApT[tid];
    if (tid < 32) s_pw1[tid] = pos_w1[tid];

    const int d  = tid & 63;
    const int j  = tid & 7;
    const int vA = (tid >> 3) & 7;
    const int ln = tid >> 6;          // pair id: 0 or 1
    const int barid = 1 + ln;

    // ---- per-thread register weights ----
    float2 wv2[32];
    {
        const float* wvg = v_tbl + e * 4096 + d * 64;
        #pragma unroll
        for (int c4 = 0; c4 < 16; ++c4) {
            const float4 t4 = *reinterpret_cast<const float4*>(wvg + 4 * c4);
            wv2[2 * c4]     = mf2(t4.x, t4.y);
            wv2[2 * c4 + 1] = mf2(t4.z, t4.w);
        }
    }
    float2 aw2r[4], pw2r[4];
    #pragma unroll
    for (int p = 0; p < 4; ++p) {
        aw2r[p] = mf2(attn_w2[(2 * p) * 64 + d], attn_w2[(2 * p + 1) * 64 + d]);
        pw2r[p] = mf2(pos_w2[(2 * p) * 64 + d], pos_w2[(2 * p + 1) * 64 + d]);
    }
    const float sd   = g_s[d];
    const float ab2d = attn_b2[d];
    const float obd  = out_b[d];
    const float pb2d = pos_b2[d];
    const float cbj  = g_cb[j];
    const float pb1j = pos_b1[j];

    for (int chunk = 0; chunk < 4; ++chunk) {
        const int bb = chunk & 1;
        const long base_n = (long)b * 64 + nbase + chunk * 4;

        CPWAIT0();
        __syncthreads();   // CTA-wide: buffers ready, prior readers done

        // ---- prefetch next chunk ----
        if (chunk < 3) {
            const long bn1 = base_n + 4;
            const float4* kg = (const float4*)(k + bn1 * 512);
            #pragma unroll
            for (int r = 0; r < 4; ++r) {
                const int i = tid + 128 * r;
                CP16(su32(&s_k[1 - bb][(i >> 4) * 68 + (i & 15) * 4]), kg + i);
            }
            if (tid < 64) CP16(su32(&s_q[1 - bb][tid * 4]),   (const float4*)(q + bn1 * 64) + tid);
            if (tid < 32) CP16(su32(&s_pos[1 - bb][tid * 4]), (const float4*)(pos + bn1 * 32) + tid);
            if (tid < 8)  CP16(su32(&s_mask[1 - bb][tid * 4]), (const int4*)(mask + bn1 * 8) + tid);
            CPCOMMIT();
        }

        // ---- phase A1: pos-MLP hidden (+ q-fold) for rows ln, ln+2 ----
        #pragma unroll
        for (int r2 = 0; r2 < 2; ++r2) {
            const int row = ln + 2 * r2;
            const int rv = row * 8 + vA;
            const float4 p4 = *reinterpret_cast<const float4*>(&s_pos[bb][rv * 4]);
            float acc = pb1j;
            acc += p4.x * s_pw1[0 * 8 + j];
            acc += p4.y * s_pw1[1 * 8 + j];
            acc += p4.z * s_pw1[2 * 8 + j];
            acc += p4.w * s_pw1[3 * 8 + j];
            s_ph[rv * 8 + j] = fmaxf(acc, 0.f);
        }
        if (vA == 0) {
            #pragma unroll
            for (int r2 = 0; r2 < 2; ++r2) {
                const int row = ln + 2 * r2;
                float2 a0 = mf2(0.f, 0.f), a1 = mf2(0.f, 0.f);
                const float4* qr = reinterpret_cast<const float4*>(&s_q[bb][row * 64]);
                const float4* ar = reinterpret_cast<const float4*>(s_aqT + j * 68);
                #pragma unroll
                for (int c4 = 0; c4 < 16; ++c4) {
                    const float4 qq = qr[c4], aa = ar[c4];
                    a0 = ffma2(mf2(qq.x, qq.y), mf2(aa.x, aa.y), a0);
                    a1 = ffma2(mf2(qq.z, qq.w), mf2(aa.z, aa.w), a1);
                }
                s_h1q[row * 8 + j] = (a0.x + a1.x) + (a0.y + a1.y);
            }
        }
        PAIRBAR(barid);

        // ---- phase A2: attn hidden (folded) for rows ln, ln+2 ----
        #pragma unroll
        for (int r2 = 0; r2 < 2; ++r2) {
            const int row = ln + 2 * r2;
            const int rv = row * 8 + vA;
            float2 acc0 = mf2(cbj - s_h1q[row * 8 + j], 0.f);
            float2 acc1 = mf2(0.f, 0.f);
            const float4* kr = reinterpret_cast<const float4*>(&s_k[bb][rv * 68]);
            const float4* ar = reinterpret_cast<const float4*>(s_akT + j * 68);
            #pragma unroll
            for (int c4 = 0; c4 < 16; ++c4) {
                const float4 kk = kr[c4], aa = ar[c4];
                acc0 = ffma2(mf2(kk.x, kk.y), mf2(aa.x, aa.y), acc0);
                acc1 = ffma2(mf2(kk.z, kk.w), mf2(aa.z, aa.w), acc1);
            }
            const float4* phr = reinterpret_cast<const float4*>(s_ph + rv * 8);
            const float4  h0 = phr[0], h1 = phr[1];
            const float4* apr = reinterpret_cast<const float4*>(s_apT + j * 8);
            const float4  a0 = apr[0], a1 = apr[1];
            acc0 = ffma2(mf2(h0.x, h0.y), mf2(a0.x, a0.y), acc0);
            acc1 = ffma2(mf2(h0.z, h0.w), mf2(a0.z, a0.w), acc1);
            acc0 = ffma2(mf2(h1.x, h1.y), mf2(a1.x, a1.y), acc0);
            acc1 = ffma2(mf2(h1.z, h1.w), mf2(a1.z, a1.w), acc1);
            s_hh[rv * 8 + j] = fmaxf((acc0.x + acc1.x) + (acc0.y + acc1.y), 0.f);
        }
        PAIRBAR(barid);

        // ---- phase B: logits + vh + p, softmax; rows ln, ln+2 sequentially ----
        #pragma unroll
        for (int r2 = 0; r2 < 2; ++r2) {
            const int row = ln + 2 * r2;
            const int4 m0i = *reinterpret_cast<const int4*>(&s_mask[bb][row * 8]);
            const int4 m1i = *reinterpret_cast<const int4*>(&s_mask[bb][row * 8 + 4]);
            int mbits = 0;
            mbits |= (m0i.x != 0) << 0; mbits |= (m0i.y != 0) << 1;
            mbits |= (m0i.z != 0) << 2; mbits |= (m0i.w != 0) << 3;
            mbits |= (m1i.x != 0) << 4; mbits |= (m1i.y != 0) << 5;
            mbits |= (m1i.z != 0) << 6; mbits |= (m1i.w != 0) << 7;

            float logit[8], val[8];
            #pragma unroll
            for (int v = 0; v < 8; ++v) {
                const int rv = row * 8 + v;
                const float4* hhr = reinterpret_cast<const float4*>(s_hh + rv * 8);
                const float4 h0 = hhr[0], h1 = hhr[1];
                float2 a2 = ffma2(mf2(h0.x, h0.y), aw2r[0], mf2(ab2d, 0.f));
                float2 a3 = ffma2(mf2(h0.z, h0.w), aw2r[1], mf2(0.f, 0.f));
                a2 = ffma2(mf2(h1.x, h1.y), aw2r[2], a2);
                a3 = ffma2(mf2(h1.z, h1.w), aw2r[3], a3);

                const float4* phr = reinterpret_cast<const float4*>(s_ph + rv * 8);
                const float4 p0 = phr[0], p1 = phr[1];
                float2 pv = ffma2(mf2(p0.x, p0.y), pw2r[0], mf2(pb2d, 0.f));
                float2 pw = ffma2(mf2(p0.z, p0.w), pw2r[1], mf2(0.f, 0.f));
                pv = ffma2(mf2(p1.x, p1.y), pw2r[2], pv);
                pw = ffma2(mf2(p1.z, p1.w), pw2r[3], pw);

                float2 va = mf2(sd, 0.f), vb = mf2(0.f, 0.f);
                float2 vc = mf2(0.f, 0.f), vd4 = mf2(0.f, 0.f);
                const float4* kr4 = reinterpret_cast<const float4*>(&s_k[bb][rv * 68]);
                #pragma unroll
                for (int c4 = 0; c4 < 16; c4 += 2) {
                    const float4 k0 = kr4[c4], k1 = kr4[c4 + 1];
                    va  = ffma2(mf2(k0.x, k0.y), wv2[2 * c4],     va);
                    vb  = ffma2(mf2(k0.z, k0.w), wv2[2 * c4 + 1], vb);
                    vc  = ffma2(mf2(k1.x, k1.y), wv2[2 * c4 + 2], vc);
                    vd4 = ffma2(mf2(k1.z, k1.w), wv2[2 * c4 + 3], vd4);
                }
                const float vh = ((va.x + vb.x) + (vc.x + vd4.x))
                               + ((va.y + vb.y) + (vc.y + vd4.y));
                logit[v] = ((mbits >> v) & 1) ? ((a2.x + a3.x) + (a2.y + a3.y)) : -1e9f;
                val[v] = vh + (pv.x + pw.x) + (pv.y + pw.y);
            }
            const float m01 = fmaxf(fmaxf(logit[0], logit[1]), fmaxf(logit[2], logit[3]));
            const float m23 = fmaxf(fmaxf(logit[4], logit[5]), fmaxf(logit[6], logit[7]));
            const float m = fmaxf(m01, m23);
            float ev[8];
            #pragma unroll
            for (int v = 0; v < 8; ++v) ev[v] = __expf(logit[v] - m);
            const float ssum = ((ev[0] + ev[1]) + (ev[2] + ev[3]))
                             + ((ev[4] + ev[5]) + (ev[6] + ev[7]));
            const float wacc = ((ev[0] * val[0] + ev[1] * val[1]) + (ev[2] * val[2] + ev[3] * val[3]))
                             + ((ev[4] * val[4] + ev[5] * val[5]) + (ev[6] * val[6] + ev[7] * val[7]));
            s_x[row * 64 + d] = __fdividef(wacc, ssum);
        }
        PAIRBAR(barid);

        // ---- output GEMM, both rows share weight reads ----
        {
            float a0 = obd, a1 = 0.f, a2 = 0.f, a3 = 0.f;
            float b0 = obd, b1 = 0.f, b2 = 0.f, b3 = 0.f;
            const float4* xr0 = reinterpret_cast<const float4*>(s_x + ln * 64);
            const float4* xr1 = reinterpret_cast<const float4*>(s_x + (ln + 2) * 64);
            const float* wc = s_ow + d;
            #pragma unroll
            for (int c4 = 0; c4 < 16; ++c4) {
                const float4 x0 = xr0[c4], x1 = xr1[c4];
                const float w0 = wc[(4 * c4 + 0) * 64];
                const float w1 = wc[(4 * c4 + 1) * 64];
                const float w2 = wc[(4 * c4 + 2) * 64];
                const float w3 = wc[(4 * c4 + 3) * 64];
                a0 += x0.x * w0; b0 += x1.x * w0;
                a1 += x0.y * w1; b1 += x1.y * w1;
                a2 += x0.z * w2; b2 += x1.z * w2;
                a3 += x0.w * w3; b3 += x1.w * w3;
            }
            out[(base_n + ln) * 64 + d]     = (a0 + a1) + (a2 + a3);
            out[(base_n + ln + 2) * 64 + d] = (b0 + b1) + (b2 + b3);
        }
        // next chunk's CPWAIT0+__syncthreads closes this chunk
    }
}

extern "C" void kernel_launch(void* const* d_in, const int* in_sizes, int n_in,
                              void* d_out, int out_size)
{
    const float* q        = (const float*)d_in[0];
    const float* k        = (const float*)d_in[1];
    const float* pos      = (const float*)d_in[2];
    const float* strength = (const float*)d_in[3];
    const float* q_tbl    = (const float*)d_in[4];
    const float* k_tbl    = (const float*)d_in[5];
    const float* v_tbl    = (const float*)d_in[6];
    const float* pos_w1   = (const float*)d_in[7];
    const float* pos_b1   = (const float*)d_in[8];
    const float* pos_w2   = (const float*)d_in[9];
    const float* pos_b2   = (const float*)d_in[10];
    const float* attn_w1  = (const float*)d_in[11];
    const float* attn_b1  = (const float*)d_in[12];
    const float* attn_w2  = (const float*)d_in[13];
    const float* attn_b2  = (const float*)d_in[14];
    const float* out_w    = (const float*)d_in[15];
    const float* out_b    = (const float*)d_in[16];
    const float* str_w    = (const float*)d_in[17];
    const float* str_b    = (const float*)d_in[18];
    const int*   mask     = (const int*)d_in[19];
    const int*   embed_id = (const int*)d_in[20];
    float* out = (float*)d_out;

    precompute_kernel<<<1, 256>>>(strength, str_w, str_b, q_tbl, k_tbl,
                                  attn_w1, attn_b1, pos_w2, pos_b2, embed_id);

    dim3 grid(BQ, 4);
    attn_main<<<grid, 128>>>(q, k, pos, v_tbl,
                             pos_w1, pos_b1, pos_w2, pos_b2,
                             attn_w2, attn_b2, out_w, out_b,
                             mask, embed_id, out);
}

// round 6
// speedup vs baseline: 1.2964x; 1.2964x over previous
#include <cuda_runtime.h>
#include <cuda_bf16.h>

#define BQ 1024

// ---------- packed fp32x2 FMA (Blackwell FFMA2) ----------
union F2U { float2 f; unsigned long long u; };
__device__ __forceinline__ float2 ffma2(float2 a, float2 b, float2 c) {
    F2U A, B, C, D;
    A.f = a; B.f = b; C.f = c;
    asm("fma.rn.f32x2 %0, %1, %2, %3;" : "=l"(D.u) : "l"(A.u), "l"(B.u), "l"(C.u));
    return D.f;
}
__device__ __forceinline__ float2 mf2(float x, float y) { float2 r; r.x = x; r.y = y; return r; }

// ---------- cp.async helpers ----------
__device__ __forceinline__ unsigned su32(const void* p) {
    return (unsigned)__cvta_generic_to_shared(p);
}
#define CP16(dst_u32, src_ptr) \
    asm volatile("cp.async.cg.shared.global [%0], [%1], 16;\n" :: "r"(dst_u32), "l"(src_ptr))
#define CPCOMMIT() asm volatile("cp.async.commit_group;\n" ::: "memory")
#define CPWAIT0()  asm volatile("cp.async.wait_group 0;\n" ::: "memory")

// ---------- dynamic smem layout (floats) ----------
#define OFF_OW    0        // 4096   out_w [c][d]
#define OFF_K     4096     // 2*2176 k rows stride 68, dbl buffered
#define OFF_AKT   8448     // 544    [j][c] stride 68
#define OFF_AQT   8992     // 544
#define OFF_Q     9536     // 2*256
#define OFF_POS   10048    // 2*128
#define OFF_PH    10304    // 256
#define OFF_HH    10560    // 256
#define OFF_X     10816    // 256
#define OFF_APT   11072    // 64
#define OFF_WV    11136    // 4160   Wv[c][d] stride 65
#define OFF_H1Q   15296    // 32
#define OFF_PW1   15328    // 32
#define OFF_MASK  15360    // 2*32 ints
#define OFF_MBITS 15424    // 4 ints
#define SMEM_FLOATS 15432
#define SMEM_BYTES  (SMEM_FLOATS * 4)

// Folded-weight device globals
__device__ float g_s[64];      // strength @ str_w + str_b
__device__ float g_AkT[512];   // [j][c] = sum_d Wk[d][c] * attn_w1[d][j]
__device__ float g_AqT[512];   // [j][c]
__device__ float g_ApT[64];    // [j][i] = sum_d pos_w2[i][d] * attn_w1[d][j]
__device__ float g_cb[8];      // [j]

__global__ void precompute_kernel(
    const float* __restrict__ strength, const float* __restrict__ str_w,
    const float* __restrict__ str_b,
    const float* __restrict__ q_tbl, const float* __restrict__ k_tbl,
    const float* __restrict__ attn_w1, const float* __restrict__ attn_b1,
    const float* __restrict__ pos_w2, const float* __restrict__ pos_b2,
    const int* __restrict__ embed_id)
{
    const int t = threadIdx.x;
    const int e = embed_id[0];

    if (t < 64) {
        float acc = str_b[t];
        for (int i = 0; i < 512; ++i) acc += strength[i] * str_w[i * 64 + t];
        g_s[t] = acc;
    }
    for (int idx = t; idx < 512; idx += 256) {
        const int j = idx >> 6, c = idx & 63;
        float ak = 0.f, aq = 0.f;
        for (int dd = 0; dd < 64; ++dd) {
            const float w1 = attn_w1[dd * 8 + j];
            ak += k_tbl[e * 4096 + dd * 64 + c] * w1;
            aq += q_tbl[e * 4096 + dd * 64 + c] * w1;
        }
        g_AkT[idx] = ak;
        g_AqT[idx] = aq;
    }
    if (t < 64) {
        const int j = t >> 3, i = t & 7;
        float ap = 0.f;
        for (int dd = 0; dd < 64; ++dd) ap += pos_w2[i * 64 + dd] * attn_w1[dd * 8 + j];
        g_ApT[j * 8 + i] = ap;
    }
    if (t < 8) {
        float cb = attn_b1[t];
        for (int dd = 0; dd < 64; ++dd) cb += pos_b2[dd] * attn_w1[dd * 8 + t];
        g_cb[t] = cb;
    }
}

__global__ __launch_bounds__(256, 3)
void attn_main(
    const float* __restrict__ q, const float* __restrict__ k,
    const float* __restrict__ pos,
    const float* __restrict__ v_tbl,
    const float* __restrict__ pos_w1, const float* __restrict__ pos_b1,
    const float* __restrict__ pos_w2, const float* __restrict__ pos_b2,
    const float* __restrict__ attn_w2, const float* __restrict__ attn_b2,
    const float* __restrict__ out_w, const float* __restrict__ out_b,
    const int* __restrict__ mask, const int* __restrict__ embed_id,
    float* __restrict__ out)
{
    extern __shared__ __align__(16) float sm[];
    float* s_ow  = sm + OFF_OW;
    float* s_kb  = sm + OFF_K;      // + bb*2176
    float* s_akT = sm + OFF_AKT;
    float* s_aqT = sm + OFF_AQT;
    float* s_qb  = sm + OFF_Q;      // + bb*256
    float* s_posb= sm + OFF_POS;    // + bb*128
    float* s_ph  = sm + OFF_PH;
    float* s_hh  = sm + OFF_HH;
    float* s_x   = sm + OFF_X;
    float* s_apT = sm + OFF_APT;
    float* s_wv  = sm + OFF_WV;     // [c*65 + d]
    float* s_h1q = sm + OFF_H1Q;
    float* s_pw1 = sm + OFF_PW1;
    int*   s_mask  = (int*)(sm + OFF_MASK);   // + bb*32
    int*   s_mbits = (int*)(sm + OFF_MBITS);

    const int tid = threadIdx.x;
    const int b = blockIdx.x;
    const int nbase = blockIdx.y * 32;
    const int e = embed_id[0];

    // ---- prefetch chunk 0 ----
    {
        const long base_n = (long)b * 64 + nbase;
        const float4* kg = (const float4*)(k + base_n * 512);
        int i = tid;
        CP16(su32(&s_kb[(i >> 4) * 68 + (i & 15) * 4]), kg + i);
        i = tid + 256;
        CP16(su32(&s_kb[(i >> 4) * 68 + (i & 15) * 4]), kg + i);
        if (tid < 64) CP16(su32(&s_qb[tid * 4]),   (const float4*)(q + base_n * 64) + tid);
        if (tid < 32) CP16(su32(&s_posb[tid * 4]), (const float4*)(pos + base_n * 32) + tid);
        if (tid < 8)  CP16(su32(&s_mask[tid * 4]), (const int4*)(mask + base_n * 8) + tid);
        CPCOMMIT();
    }

    // ---- one-time staging ----
    for (int i = tid; i < 4096; i += 256) s_ow[i] = out_w[i];          // [c][d]
    {
        const float* wvg = v_tbl + e * 4096;
        for (int i = tid; i < 4096; i += 256) {
            const int dd = i >> 6, c = i & 63;
            s_wv[c * 65 + dd] = wvg[i];                                // conflict-free both ways
        }
    }
    for (int i = tid; i < 512; i += 256) {
        const int jj = i >> 6, c = i & 63;
        s_akT[jj * 68 + c] = g_AkT[i];
        s_aqT[jj * 68 + c] = g_AqT[i];
    }
    if (tid < 64) s_apT[tid] = g_ApT[tid];
    if (tid < 32) s_pw1[tid] = pos_w1[tid];

    const int d  = tid & 63;
    const int j  = tid & 7;
    const int vA = (tid >> 3) & 7;
    const int ln = tid >> 6;
    const int ln8v = ln * 8 + vA;

    float2 aw2r[4], pw2r[4];
    #pragma unroll
    for (int p = 0; p < 4; ++p) {
        aw2r[p] = mf2(attn_w2[(2 * p) * 64 + d], attn_w2[(2 * p + 1) * 64 + d]);
        pw2r[p] = mf2(pos_w2[(2 * p) * 64 + d], pos_w2[(2 * p + 1) * 64 + d]);
    }
    const float sd   = g_s[d];
    const float ab2d = attn_b2[d];
    const float obd  = out_b[d];
    const float pb2d = pos_b2[d];
    const float cbj  = g_cb[j];
    const float pb1j = pos_b1[j];

    for (int chunk = 0; chunk < 8; ++chunk) {
        const int bb = chunk & 1;
        const long base_n = (long)b * 64 + nbase + chunk * 4;
        float* s_k   = s_kb + bb * 2176;
        float* s_q   = s_qb + bb * 256;
        float* s_pos = s_posb + bb * 128;
        int*   s_msk = s_mask + bb * 32;

        CPWAIT0();
        __syncthreads();

        // ---- prefetch next chunk ----
        if (chunk < 7) {
            const long bn1 = base_n + 4;
            float* n_k   = s_kb + (1 - bb) * 2176;
            float* n_q   = s_qb + (1 - bb) * 256;
            float* n_pos = s_posb + (1 - bb) * 128;
            int*   n_msk = s_mask + (1 - bb) * 32;
            const float4* kg = (const float4*)(k + bn1 * 512);
            int i = tid;
            CP16(su32(&n_k[(i >> 4) * 68 + (i & 15) * 4]), kg + i);
            i = tid + 256;
            CP16(su32(&n_k[(i >> 4) * 68 + (i & 15) * 4]), kg + i);
            if (tid < 64) CP16(su32(&n_q[tid * 4]),   (const float4*)(q + bn1 * 64) + tid);
            if (tid < 32) CP16(su32(&n_pos[tid * 4]), (const float4*)(pos + bn1 * 32) + tid);
            if (tid < 8)  CP16(su32(&n_msk[tid * 4]), (const int4*)(mask + bn1 * 8) + tid);
            CPCOMMIT();
        }

        // ---- phase A1: pos-MLP hidden + q-fold + mask pack ----
        {
            const float4 p4 = *reinterpret_cast<const float4*>(&s_pos[ln8v * 4]);
            float acc = pb1j;
            acc += p4.x * s_pw1[0 * 8 + j];
            acc += p4.y * s_pw1[1 * 8 + j];
            acc += p4.z * s_pw1[2 * 8 + j];
            acc += p4.w * s_pw1[3 * 8 + j];
            s_ph[ln8v * 8 + j] = fmaxf(acc, 0.f);
        }
        if (vA == 0) {
            float2 a0 = mf2(0.f, 0.f), a1 = mf2(0.f, 0.f);
            const float4* qr = reinterpret_cast<const float4*>(&s_q[ln * 64]);
            const float4* ar = reinterpret_cast<const float4*>(s_aqT + j * 68);
            #pragma unroll
            for (int c4 = 0; c4 < 16; ++c4) {
                const float4 qq = qr[c4], aa = ar[c4];
                a0 = ffma2(mf2(qq.x, qq.y), mf2(aa.x, aa.y), a0);
                a1 = ffma2(mf2(qq.z, qq.w), mf2(aa.z, aa.w), a1);
            }
            s_h1q[ln * 8 + j] = (a0.x + a1.x) + (a0.y + a1.y);
        }
        if (tid < 4) {
            const int4 m0 = *reinterpret_cast<const int4*>(&s_msk[tid * 8]);
            const int4 m1 = *reinterpret_cast<const int4*>(&s_msk[tid * 8 + 4]);
            int bits = 0;
            bits |= (m0.x != 0) << 0; bits |= (m0.y != 0) << 1;
            bits |= (m0.z != 0) << 2; bits |= (m0.w != 0) << 3;
            bits |= (m1.x != 0) << 4; bits |= (m1.y != 0) << 5;
            bits |= (m1.z != 0) << 6; bits |= (m1.w != 0) << 7;
            s_mbits[tid] = bits;
        }
        __syncthreads();

        // ---- phase A2: attn hidden (folded) ----
        {
            float2 acc0 = mf2(cbj - s_h1q[ln * 8 + j], 0.f);
            float2 acc1 = mf2(0.f, 0.f);
            const float4* kr = reinterpret_cast<const float4*>(&s_k[ln8v * 68]);
            const float4* ar = reinterpret_cast<const float4*>(s_akT + j * 68);
            #pragma unroll
            for (int c4 = 0; c4 < 16; ++c4) {
                const float4 kk = kr[c4], aa = ar[c4];
                acc0 = ffma2(mf2(kk.x, kk.y), mf2(aa.x, aa.y), acc0);
                acc1 = ffma2(mf2(kk.z, kk.w), mf2(aa.z, aa.w), acc1);
            }
            const float4* phr = reinterpret_cast<const float4*>(s_ph + ln8v * 8);
            const float4  h0 = phr[0], h1 = phr[1];
            const float4* apr = reinterpret_cast<const float4*>(s_apT + j * 8);
            const float4  a0 = apr[0], a1 = apr[1];
            acc0 = ffma2(mf2(h0.x, h0.y), mf2(a0.x, a0.y), acc0);
            acc1 = ffma2(mf2(h0.z, h0.w), mf2(a0.z, a0.w), acc1);
            acc0 = ffma2(mf2(h1.x, h1.y), mf2(a1.x, a1.y), acc0);
            acc1 = ffma2(mf2(h1.z, h1.w), mf2(a1.z, a1.w), acc1);
            s_hh[ln8v * 8 + j] = fmaxf((acc0.x + acc1.x) + (acc0.y + acc1.y), 0.f);
        }
        __syncthreads();

        // ---- phase B ----
        {
            const int mbits = s_mbits[ln];
            // part 1: logits + pos-projection per v
            float logit[8], pvv[8];
            #pragma unroll
            for (int v = 0; v < 8; ++v) {
                const int rv = ln * 8 + v;
                const float4* hhr = reinterpret_cast<const float4*>(s_hh + rv * 8);
                const float4 h0 = hhr[0], h1 = hhr[1];
                float2 a2 = ffma2(mf2(h0.x, h0.y), aw2r[0], mf2(ab2d, 0.f));
                float2 a3 = ffma2(mf2(h0.z, h0.w), aw2r[1], mf2(0.f, 0.f));
                a2 = ffma2(mf2(h1.x, h1.y), aw2r[2], a2);
                a3 = ffma2(mf2(h1.z, h1.w), aw2r[3], a3);

                const float4* phr = reinterpret_cast<const float4*>(s_ph + rv * 8);
                const float4 p0 = phr[0], p1 = phr[1];
                float2 pv = ffma2(mf2(p0.x, p0.y), pw2r[0], mf2(pb2d, 0.f));
                float2 pw = ffma2(mf2(p0.z, p0.w), pw2r[1], mf2(0.f, 0.f));
                pv = ffma2(mf2(p1.x, p1.y), pw2r[2], pv);
                pw = ffma2(mf2(p1.z, p1.w), pw2r[3], pw);

                logit[v] = ((mbits >> v) & 1) ? ((a2.x + a3.x) + (a2.y + a3.y)) : -1e9f;
                pvv[v] = (pv.x + pw.x) + (pv.y + pw.y);
            }
            // part 2: vh for all 8 v, c4-outer with shared-resident Wv
            float2 vh2[8];
            #pragma unroll
            for (int v = 0; v < 8; ++v) vh2[v] = mf2(sd, 0.f);
            const float* wcol = s_wv + d;
            const float4* krow = reinterpret_cast<const float4*>(s_k + ln * 8 * 68);
            #pragma unroll
            for (int c4 = 0; c4 < 16; ++c4) {
                const float2 wA = mf2(wcol[(4 * c4 + 0) * 65], wcol[(4 * c4 + 1) * 65]);
                const float2 wB = mf2(wcol[(4 * c4 + 2) * 65], wcol[(4 * c4 + 3) * 65]);
                #pragma unroll
                for (int v = 0; v < 8; ++v) {
                    const float4 k4 = krow[v * 17 + c4];   // 68 floats = 17 float4
                    vh2[v] = ffma2(mf2(k4.x, k4.y), wA, vh2[v]);
                    vh2[v] = ffma2(mf2(k4.z, k4.w), wB, vh2[v]);
                }
            }
            // softmax over V
            const float m01 = fmaxf(fmaxf(logit[0], logit[1]), fmaxf(logit[2], logit[3]));
            const float m23 = fmaxf(fmaxf(logit[4], logit[5]), fmaxf(logit[6], logit[7]));
            const float m = fmaxf(m01, m23);
            float ev[8], val[8];
            #pragma unroll
            for (int v = 0; v < 8; ++v) {
                ev[v] = __expf(logit[v] - m);
                val[v] = (vh2[v].x + vh2[v].y) + pvv[v];
            }
            const float ssum = ((ev[0] + ev[1]) + (ev[2] + ev[3]))
                             + ((ev[4] + ev[5]) + (ev[6] + ev[7]));
            const float wacc = ((ev[0] * val[0] + ev[1] * val[1]) + (ev[2] * val[2] + ev[3] * val[3]))
                             + ((ev[4] * val[4] + ev[5] * val[5]) + (ev[6] * val[6] + ev[7] * val[7]));
            s_x[ln * 64 + d] = __fdividef(wacc, ssum);
        }
        __syncthreads();

        // ---- output GEMM: y = x @ out_w + out_b ([c][d], conflict-free) ----
        {
            float acc0 = obd, acc1 = 0.f, acc2 = 0.f, acc3 = 0.f;
            const float4* xr = reinterpret_cast<const float4*>(s_x + ln * 64);
            const float* wc = s_ow + d;
            #pragma unroll
            for (int c4 = 0; c4 < 16; ++c4) {
                const float4 xx = xr[c4];
                acc0 += xx.x * wc[(4 * c4 + 0) * 64];
                acc1 += xx.y * wc[(4 * c4 + 1) * 64];
                acc2 += xx.z * wc[(4 * c4 + 2) * 64];
                acc3 += xx.w * wc[(4 * c4 + 3) * 64];
            }
            out[(base_n + ln) * 64 + d] = (acc0 + acc1) + (acc2 + acc3);
        }
        __syncthreads();
    }
}

extern "C" void kernel_launch(void* const* d_in, const int* in_sizes, int n_in,
                              void* d_out, int out_size)
{
    const float* q        = (const float*)d_in[0];
    const float* k        = (const float*)d_in[1];
    const float* pos      = (const float*)d_in[2];
    const float* strength = (const float*)d_in[3];
    const float* q_tbl    = (const float*)d_in[4];
    const float* k_tbl    = (const float*)d_in[5];
    const float* v_tbl    = (const float*)d_in[6];
    const float* pos_w1   = (const float*)d_in[7];
    const float* pos_b1   = (const float*)d_in[8];
    const float* pos_w2   = (const float*)d_in[9];
    const float* pos_b2   = (const float*)d_in[10];
    const float* attn_w1  = (const float*)d_in[11];
    const float* attn_b1  = (const float*)d_in[12];
    const float* attn_w2  = (const float*)d_in[13];
    const float* attn_b2  = (const float*)d_in[14];
    const float* out_w    = (const float*)d_in[15];
    const float* out_b    = (const float*)d_in[16];
    const float* str_w    = (const float*)d_in[17];
    const float* str_b    = (const float*)d_in[18];
    const int*   mask     = (const int*)d_in[19];
    const int*   embed_id = (const int*)d_in[20];
    float* out = (float*)d_out;

    static bool attr_set = false;
    if (!attr_set) {
        cudaFuncSetAttribute(attn_main, cudaFuncAttributeMaxDynamicSharedMemorySize, SMEM_BYTES);
        attr_set = true;
    }

    precompute_kernel<<<1, 256>>>(strength, str_w, str_b, q_tbl, k_tbl,
                                  attn_w1, attn_b1, pos_w2, pos_b2, embed_id);

    dim3 grid(BQ, 2);
    attn_main<<<grid, 256, SMEM_BYTES>>>(q, k, pos, v_tbl,
                                         pos_w1, pos_b1, pos_w2, pos_b2,
                                         attn_w2, attn_b2, out_w, out_b,
                                         mask, embed_id, out);
}